// round 3
// baseline (speedup 1.0000x reference)
#include <cuda_runtime.h>
#include <math.h>

#define G      1024
#define GI     (G - 2)          // 1022 interior
#define B      4
#define N_TOT  (B * G * G)

// iteration-invariant fields (padded G x G layout, stride G)
__device__ float g_w  [N_TOT];   // exp(mu * prev_pre)
__device__ float g_h  [N_TOT];   // 0.5 / y3   (0 on boundary)
__device__ float g_F  [N_TOT];   // f * H^2 / y3 (0 on boundary)
// ping-pong solution buffers, zero boundary
__device__ float g_u0 [N_TOT];
__device__ float g_u1 [N_TOT];

// ------------------------ precompute ------------------------
__global__ void k_w(const float* __restrict__ prev, const float* __restrict__ mu) {
    int idx = blockIdx.x * blockDim.x + threadIdx.x;
    if (idx >= N_TOT) return;
    g_w[idx] = expf(mu[0] * prev[idx]);
}

__global__ void k_init(const float* __restrict__ pre) {
    int j = blockIdx.x * blockDim.x + threadIdx.x;
    int i = blockIdx.y;
    int b = blockIdx.z;
    if (j >= G) return;
    int idx = (b * G + i) * G + j;
    float v = 0.0f;
    if (i >= 1 && i <= G - 2 && j >= 1 && j <= G - 2)
        v = pre[(b * GI + (i - 1)) * GI + (j - 1)];
    g_u0[idx] = v;
    g_u1[idx] = 0.0f;
}

__global__ void k_coef(const float* __restrict__ f) {
    int j = blockIdx.x * blockDim.x + threadIdx.x;
    int i = blockIdx.y;
    int b = blockIdx.z;
    if (j >= G) return;
    int idx = (b * G + i) * G + j;
    if (i < 1 || i > G - 2 || j < 1 || j > G - 2) {
        g_h[idx] = 0.0f; g_F[idx] = 0.0f;
        return;
    }
    float wc = g_w[idx];
    float y3  = 0.5f * (g_w[idx - G] + g_w[idx + G] + g_w[idx - 1] + g_w[idx + 1]) + 2.0f * wc;
    float iy3 = 1.0f / y3;
    const float HH = (1.0f / 1023.0f) * (1.0f / 1023.0f);
    g_h[idx] = 0.5f * iy3;
    g_F[idx] = f[idx] * HH * iy3;
}

// ------------------------ single plain sweep (first step) ------------------------
__global__ void k_step(int parity) {
    int j0 = (blockIdx.x * blockDim.x + threadIdx.x) * 4;
    int i  = blockIdx.y * blockDim.y + threadIdx.y + 1;
    int b  = blockIdx.z;
    if (i > G - 2) return;
    int idx = (b * G + i) * G + j0;

    const float* __restrict__ u = parity ? g_u1 : g_u0;
    float4 uC4 = *(const float4*)(u + idx);
    float4 uN4 = *(const float4*)(u + idx - G);
    float4 uS4 = *(const float4*)(u + idx + G);
    float  uLl = u[idx - 1];
    float  uRr = u[idx + 4];
    float4 wC4 = *(const float4*)(g_w + idx);
    float4 wN4 = *(const float4*)(g_w + idx - G);
    float4 wS4 = *(const float4*)(g_w + idx + G);
    float  wLl = g_w[idx - 1];
    float  wRr = g_w[idx + 4];
    float4 h4 = *(const float4*)(g_h + idx);
    float4 F4 = *(const float4*)(g_F + idx);

    float uc[6] = { uLl, uC4.x, uC4.y, uC4.z, uC4.w, uRr };
    float wc[6] = { wLl, wC4.x, wC4.y, wC4.z, wC4.w, wRr };
    float un[4] = { uN4.x, uN4.y, uN4.z, uN4.w };
    float us[4] = { uS4.x, uS4.y, uS4.z, uS4.w };
    float wn[4] = { wN4.x, wN4.y, wN4.z, wN4.w };
    float ws[4] = { wS4.x, wS4.y, wS4.z, wS4.w };
    float hh[4] = { h4.x, h4.y, h4.z, h4.w };
    float ff[4] = { F4.x, F4.y, F4.z, F4.w };

    float r[4];
#pragma unroll
    for (int k = 0; k < 4; ++k) {
        float uW = uc[k], uE = uc[k + 2];
        float s = wc[k + 1] * (uW + uE + un[k] + us[k]);
        s = fmaf(wc[k],     uW,    s);
        s = fmaf(wc[k + 2], uE,    s);
        s = fmaf(wn[k],     un[k], s);
        s = fmaf(ws[k],     us[k], s);
        r[k] = fmaf(hh[k], s, ff[k]);
    }

    float* __restrict__ dst = parity ? g_u0 : g_u1;
    if (j0 == 0) {
        dst[idx + 1] = r[1]; dst[idx + 2] = r[2]; dst[idx + 3] = r[3];
    } else if (j0 == G - 4) {
        dst[idx] = r[0]; dst[idx + 1] = r[1]; dst[idx + 2] = r[2];
    } else {
        *(float4*)(dst + idx) = make_float4(r[0], r[1], r[2], r[3]);
    }
}

// ------------------------ fused 2-step kernel ------------------------
__device__ __forceinline__ float4 ld4g(const float* __restrict__ base, int row, int col) {
    if ((unsigned)row < (unsigned)G) return *(const float4*)(base + row * G + col);
    return make_float4(0.f, 0.f, 0.f, 0.f);
}
__device__ __forceinline__ float ldsg(const float* __restrict__ base, int row, int col) {
    if ((unsigned)row < (unsigned)G) return base[row * G + col];
    return 0.f;
}

// 4-wide weighted 5-point stencil: r = h*(wC*(uW+uE+uN+uS) + wW*uW + wE*uE + wN*uN + wS*uS) + F
__device__ __forceinline__ float4 stencil4(
    float4 C, float Wx, float Ex, float4 Nn, float4 Ss,
    float4 wC, float wWx, float wEx, float4 wN, float4 wS,
    float4 h, float4 F)
{
    float uc[6] = { Wx, C.x, C.y, C.z, C.w, Ex };
    float wc[6] = { wWx, wC.x, wC.y, wC.z, wC.w, wEx };
    float un[4] = { Nn.x, Nn.y, Nn.z, Nn.w };
    float us[4] = { Ss.x, Ss.y, Ss.z, Ss.w };
    float wn[4] = { wN.x, wN.y, wN.z, wN.w };
    float ws[4] = { wS.x, wS.y, wS.z, wS.w };
    float hh[4] = { h.x, h.y, h.z, h.w };
    float ff[4] = { F.x, F.y, F.z, F.w };
    float r[4];
#pragma unroll
    for (int k = 0; k < 4; ++k) {
        float uW = uc[k], uE = uc[k + 2];
        float s = wc[k + 1] * (uW + uE + un[k] + us[k]);
        s = fmaf(wc[k],     uW,    s);
        s = fmaf(wc[k + 2], uE,    s);
        s = fmaf(wn[k],     un[k], s);
        s = fmaf(ws[k],     us[k], s);
        r[k] = fmaf(hh[k], s, ff[k]);
    }
    return make_float4(r[0], r[1], r[2], r[3]);
}

// One warp = one 128-col strip x 16-row band. Two Jacobi steps fused;
// intermediate s1 lives in a 3-deep register ring; horizontal neighbors via shfl;
// strip-edge halo s1 columns computed redundantly by lanes 0 / 31.
template <bool FINAL>
__global__ void __launch_bounds__(128)
k_step2(int parity, float* __restrict__ out)
{
    const unsigned FULL = 0xffffffffu;
    int lane = threadIdx.x;
    int wid  = blockIdx.x * 4 + threadIdx.y;   // 0..2047
    int strip = wid & 7;
    int band  = (wid >> 3) & 63;
    int b     = wid >> 9;

    int c0 = strip << 7;            // 0,128,...,896
    int cb = c0 + (lane << 2);      // this lane's 4 columns
    int r0 = band << 4;             // 0,16,...,1008

    const float* __restrict__ U  = (parity ? g_u1 : g_u0) + b * G * G;
    float* __restrict__       Dd = (parity ? g_u0 : g_u1) + b * G * G;
    const float* __restrict__ W  = g_w + b * G * G;
    const float* __restrict__ Hh = g_h + b * G * G;
    const float* __restrict__ Ff = g_F + b * G * G;

    bool hasL = (c0 != 0);          // strip 0: col -1 never needed (col 0 is boundary)
    bool hasR = (c0 != 896);        // strip 7: col 1024 never needed

    float4 s1A = make_float4(0, 0, 0, 0);   // s1 row q-2
    float4 s1B = make_float4(0, 0, 0, 0);   // s1 row q-1
    float  s1HL_A = 0.f, s1HR_A = 0.f;      // halo s1 at row q-1

    for (int q = r0 - 1; q <= r0 + 16; ++q) {
        // ---- step-1 at row q ----
        float4 uC = ld4g(U, q, cb), uN = ld4g(U, q - 1, cb), uS = ld4g(U, q + 1, cb);
        float4 wC = ld4g(W, q, cb), wN = ld4g(W, q - 1, cb), wS = ld4g(W, q + 1, cb);
        float4 h4 = ld4g(Hh, q, cb), F4 = ld4g(Ff, q, cb);

        float uWx = __shfl_up_sync(FULL, uC.w, 1);
        float uEx = __shfl_down_sync(FULL, uC.x, 1);
        float wWx = __shfl_up_sync(FULL, wC.w, 1);
        float wEx = __shfl_down_sync(FULL, wC.x, 1);

        float s1HL_new = 0.f, s1HR_new = 0.f;
        if (lane == 0) {
            uWx = 0.f; wWx = 0.f;
            if (hasL) {
                float u1 = ldsg(U, q, c0 - 1),  w1 = ldsg(W, q, c0 - 1);
                uWx = u1; wWx = w1;
                float u2 = ldsg(U, q, c0 - 2),  w2 = ldsg(W, q, c0 - 2);
                float un1 = ldsg(U, q - 1, c0 - 1), us1 = ldsg(U, q + 1, c0 - 1);
                float wn1 = ldsg(W, q - 1, c0 - 1), ws1 = ldsg(W, q + 1, c0 - 1);
                float hh1 = ldsg(Hh, q, c0 - 1), ff1 = ldsg(Ff, q, c0 - 1);
                float s = w1 * (u2 + uC.x + un1 + us1);
                s = fmaf(w2, u2, s); s = fmaf(wC.x, uC.x, s);
                s = fmaf(wn1, un1, s); s = fmaf(ws1, us1, s);
                s1HL_new = fmaf(hh1, s, ff1);
            }
        }
        if (lane == 31) {
            uEx = 0.f; wEx = 0.f;
            if (hasR) {
                float u1 = ldsg(U, q, c0 + 128), w1 = ldsg(W, q, c0 + 128);
                uEx = u1; wEx = w1;
                float u2 = ldsg(U, q, c0 + 129), w2 = ldsg(W, q, c0 + 129);
                float un1 = ldsg(U, q - 1, c0 + 128), us1 = ldsg(U, q + 1, c0 + 128);
                float wn1 = ldsg(W, q - 1, c0 + 128), ws1 = ldsg(W, q + 1, c0 + 128);
                float hh1 = ldsg(Hh, q, c0 + 128), ff1 = ldsg(Ff, q, c0 + 128);
                float s = w1 * (uC.w + u2 + un1 + us1);
                s = fmaf(wC.w, uC.w, s); s = fmaf(w2, u2, s);
                s = fmaf(wn1, un1, s); s = fmaf(ws1, us1, s);
                s1HR_new = fmaf(hh1, s, ff1);
            }
        }

        float4 s1n = stencil4(uC, uWx, uEx, uN, uS, wC, wWx, wEx, wN, wS, h4, F4);

        // ---- step-2 at row p = q-1 (needs s1 rows p-1,p,p+1) ----
        if (q >= r0 + 1) {
            int p = q - 1;
            float4 wC2 = ld4g(W, p, cb), wN2 = ld4g(W, p - 1, cb), wS2 = ld4g(W, p + 1, cb);
            float4 h2 = ld4g(Hh, p, cb), F2 = ld4g(Ff, p, cb);

            float sWx = __shfl_up_sync(FULL, s1B.w, 1);
            float sEx = __shfl_down_sync(FULL, s1B.x, 1);
            float wW2 = __shfl_up_sync(FULL, wC2.w, 1);
            float wE2 = __shfl_down_sync(FULL, wC2.x, 1);
            if (lane == 0) {
                sWx = s1HL_A;
                wW2 = hasL ? ldsg(W, p, c0 - 1) : 0.f;
            }
            if (lane == 31) {
                sEx = s1HR_A;
                wE2 = hasR ? ldsg(W, p, c0 + 128) : 0.f;
            }

            float4 r2 = stencil4(s1B, sWx, sEx, s1A, s1n, wC2, wW2, wE2, wN2, wS2, h2, F2);

            if (FINAL) {
                if (p >= 1 && p <= G - 2) {
                    long obase = ((long)b * GI + (p - 1)) * GI;
                    float rr[4] = { r2.x, r2.y, r2.z, r2.w };
#pragma unroll
                    for (int k = 0; k < 4; ++k) {
                        int j = cb + k;
                        if (j >= 1 && j <= G - 2) out[obase + (j - 1)] = rr[k];
                    }
                }
            } else {
                *(float4*)(Dd + p * G + cb) = r2;
            }
        }

        s1A = s1B; s1B = s1n;
        s1HL_A = s1HL_new; s1HR_A = s1HR_new;
    }
}

extern "C" void kernel_launch(void* const* d_in, const int* in_sizes, int n_in,
                              void* d_out, int out_size) {
    const float* pre  = (const float*)d_in[0];   // [B,1,1022,1022]
    const float* f    = (const float*)d_in[1];   // [B,1,1024,1024]
    const float* mu   = (const float*)d_in[2];   // [1]
    const float* prev = (const float*)d_in[3];   // [B,1,1024,1024]
    // d_in[4] = maxiter (fixed = 20 -> 21 total steps)
    float* out = (float*)d_out;

    // precompute
    k_w<<<(N_TOT + 255) / 256, 256>>>(prev, mu);
    dim3 blk(256, 1, 1);
    dim3 grd_full((G + 255) / 256, G, B);
    k_init<<<grd_full, blk>>>(pre);
    k_coef<<<grd_full, blk>>>(f);

    // step 1: plain sweep u0 -> u1
    dim3 sblk(32, 8, 1);
    dim3 sgrd(G / 128, (GI + 7) / 8, B);
    k_step<<<sgrd, sblk>>>(0);

    // steps 2..21: ten fused 2-step launches. parity: 1 => src u1/dst u0
    // L1:u1->u0, L2:u0->u1, ..., L9:u1->u0, L10: src u0 -> writes out
    dim3 tblk(32, 4, 1);
    dim3 tgrd(2048 / 4, 1, 1);   // 512 blocks, 1 warp = strip x band x batch
    for (int k = 0; k < 9; ++k) {
        k_step2<false><<<tgrd, tblk>>>((k & 1) ? 0 : 1, nullptr);
    }
    k_step2<true><<<tgrd, tblk>>>(0, out);
}